// round 9
// baseline (speedup 1.0000x reference)
#include <cuda_runtime.h>
#include <cuda_fp16.h>
#include <math.h>
#include <stdint.h>

// Problem constants
#define BB   8
#define SS   2048
#define HH   16
#define DHH  64
#define DD   1024            // H*DH
#define MM   (BB*SS)         // 16384

#define WSCALE     256.0f
#define WSCALE_INV 0.00390625f

// ---------------- scratch (__device__ globals; allocation-free) -------------
__device__ float g_Q     [BB*SS*DD];     // Q = Q_seq @ WQ        (B,S,D)
__device__ float g_K     [BB*SS*DD];     // K = K_seq @ WK        (B,S,D)
__device__ float g_logits[BB*HH*SS];     // (B,H,S)
__device__ float g_gq    [BB*HH*DHH];
__device__ float g_gk    [BB*HH*DHH];
__device__ float g_Wt    [2*HH*DD];      // transposed Wq (slot0) / Wk (slot1)
__device__ __half g_Af16[2*MM*DD];       // fp16 A (2 slots for merged GEMM1/2)
__device__ __half g_Bhi [2*DD*DD];       // split+transposed weights Bt[n,k], x256
__device__ __half g_Blo [2*DD*DD];

// ======================= PTX helpers ========================================
__device__ __forceinline__ uint32_t smem_to_u32(const void* p) {
    uint32_t a;
    asm("{ .reg .u64 t; cvta.to.shared.u64 t, %1; cvt.u32.u64 %0, t; }"
        : "=r"(a) : "l"(p));
    return a;
}
#define LDSM4(r, addr) asm volatile( \
    "ldmatrix.sync.aligned.m8n8.x4.shared.b16 {%0,%1,%2,%3}, [%4];" \
    : "=r"((r)[0]), "=r"((r)[1]), "=r"((r)[2]), "=r"((r)[3]) : "r"(addr))
#define MMA_F16(d, a, b) asm volatile( \
    "mma.sync.aligned.m16n8k16.row.col.f32.f16.f16.f32 " \
    "{%0,%1,%2,%3}, {%4,%5,%6,%7}, {%8,%9}, {%0,%1,%2,%3};" \
    : "+f"((d)[0]), "+f"((d)[1]), "+f"((d)[2]), "+f"((d)[3]) \
    : "r"((a)[0]), "r"((a)[1]), "r"((a)[2]), "r"((a)[3]), \
      "r"((b)[0]), "r"((b)[1]))
__device__ __forceinline__ void cp16(uint32_t dst, const void* src) {
    asm volatile("cp.async.cg.shared.global [%0], [%1], 16;"
                 :: "r"(dst), "l"(src) : "memory");
}
#define CP_COMMIT()  asm volatile("cp.async.commit_group;" ::: "memory")
#define CP_WAIT_2()  asm volatile("cp.async.wait_group 2;" ::: "memory")
#define CP_WAIT_1()  asm volatile("cp.async.wait_group 1;" ::: "memory")
#define CP_WAIT_0()  asm volatile("cp.async.wait_group 0;" ::: "memory")

__device__ __forceinline__ uint32_t pack_h(float a, float b) {
    __half2 t;
    t.x = __float2half_rn(a);
    t.y = __float2half_rn(b);
    return *(uint32_t*)&t;
}

// ======================= HMMA fp16 2-term GEMM ==============================
// C[M,N=1024] = (1/256) * Af16 @ (Bhi + Blo) (+res), B pre-scaled x256.
// CTA tile 128x128, BK=32, 8 warps (warp 64x32), 4-stage cp.async pipeline,
// XOR-swizzled 64B rows (conflict-free ldmatrix), 2 CTAs/SM.
// Stage: A [128][64B] @0, B_hi @8192, B_lo @16384  (24 KB)
#define NST       4
#define STAGE_B   24576
#define GEMM_SMEM (NST * STAGE_B)     // 98304
#define KB        32                  // 1024 / 32

template<bool RES>
__global__ __launch_bounds__(256, 2) void hmma_gemm_kernel(
    const __half* __restrict__ A,
    const __half* __restrict__ Bhi, const __half* __restrict__ Blo,
    float* __restrict__ C0, float* __restrict__ C1,
    const float* __restrict__ res)
{
    extern __shared__ __align__(128) char smem[];
    const uint32_t sb = smem_to_u32(smem);
    const int tid = threadIdx.x;
    const int lane = tid & 31;
    const int wid  = tid >> 5;
    const int warpM = wid >> 2;            // 0..1
    const int warpN = wid & 3;             // 0..3
    const int colBase = blockIdx.x * 128;
    const int rowBase = blockIdx.y * 128;
    const int z = blockIdx.z;
    float* C = z ? C1 : C0;
    const size_t aZ = (size_t)z * MM * DD;
    const size_t bZ = (size_t)z * DD * DD;

    // ---- cp.async mapping: row = tid>>1, two 16B chunks per buffer
    const int crow = tid >> 1;                      // 0..127
    const int cb0  = (tid & 1) * 2;                 // chunk 0/2
    const int csel = (crow >> 1) & 3;
    const uint32_t d0 = crow * 64 + ((cb0 ^ csel) * 16);
    const uint32_t d1 = crow * 64 + (((cb0 + 1) ^ csel) * 16);
    const char* pA   = (const char*)(A   + aZ + (size_t)(rowBase + crow) * DD + cb0 * 8);
    const char* pBhi = (const char*)(Bhi + bZ + (size_t)(colBase + crow) * DD + cb0 * 8);
    const char* pBlo = (const char*)(Blo + bZ + (size_t)(colBase + crow) * DD + cb0 * 8);

    #define ISSUE(s, kb) do {                                              \
        const uint32_t bs_ = sb + (s) * STAGE_B;                           \
        const int ko_ = (kb) * 64;                                         \
        cp16(bs_ + d0,         pA   + ko_); cp16(bs_ + d1,         pA   + ko_ + 16); \
        cp16(bs_ + 8192  + d0, pBhi + ko_); cp16(bs_ + 8192  + d1, pBhi + ko_ + 16); \
        cp16(bs_ + 16384 + d0, pBlo + ko_); cp16(bs_ + 16384 + d1, pBlo + ko_ + 16); \
        CP_COMMIT();                                                       \
    } while (0)

    // ---- ldmatrix swizzled addresses (within-buffer offsets)
    const int lrow = lane & 15;
    const int hi16 = lane >> 4;
    uint32_t aAddr[4][2], bAddr[2][2];
    #pragma unroll
    for (int mf = 0; mf < 4; mf++) {
        const int r = warpM * 64 + mf * 16 + lrow;
        const int s = (r >> 1) & 3;
        #pragma unroll
        for (int ks = 0; ks < 2; ks++)
            aAddr[mf][ks] = r * 64 + (((ks * 2 + hi16) ^ s) * 16);
    }
    #pragma unroll
    for (int np = 0; np < 2; np++) {
        const int r = warpN * 32 + np * 16 + lrow;
        const int s = (r >> 1) & 3;
        #pragma unroll
        for (int ks = 0; ks < 2; ks++)
            bAddr[np][ks] = r * 64 + (((ks * 2 + hi16) ^ s) * 16);
    }

    ISSUE(0, 0);
    ISSUE(1, 1);
    ISSUE(2, 2);

    float acc[4][4][4];
    #pragma unroll
    for (int mf = 0; mf < 4; mf++)
        #pragma unroll
        for (int nf = 0; nf < 4; nf++)
            #pragma unroll
            for (int q = 0; q < 4; q++) acc[mf][nf][q] = 0.f;

    for (int kb = 0; kb < KB; kb++) {
        if (kb < KB - 2)      { CP_WAIT_2(); }
        else if (kb == KB - 2){ CP_WAIT_1(); }
        else                  { CP_WAIT_0(); }
        __syncthreads();
        if (kb + 3 < KB) ISSUE((kb + 3) % NST, kb + 3);

        const uint32_t st = sb + (kb % NST) * STAGE_B;
        #pragma unroll
        for (int ks = 0; ks < 2; ks++) {
            uint32_t b0[4][2], b1[4][2];
            #pragma unroll
            for (int np = 0; np < 2; np++) {
                uint32_t r[4];
                LDSM4(r, st + 8192 + bAddr[np][ks]);       // B_hi
                b0[np * 2 + 0][0] = r[0]; b0[np * 2 + 0][1] = r[2];
                b0[np * 2 + 1][0] = r[1]; b0[np * 2 + 1][1] = r[3];
            }
            #pragma unroll
            for (int np = 0; np < 2; np++) {
                uint32_t r[4];
                LDSM4(r, st + 16384 + bAddr[np][ks]);      // B_lo
                b1[np * 2 + 0][0] = r[0]; b1[np * 2 + 0][1] = r[2];
                b1[np * 2 + 1][0] = r[1]; b1[np * 2 + 1][1] = r[3];
            }
            uint32_t a[4][4];
            #pragma unroll
            for (int mf = 0; mf < 4; mf++)
                LDSM4(a[mf], st + aAddr[mf][ks]);          // A
            #pragma unroll
            for (int mf = 0; mf < 4; mf++)
                #pragma unroll
                for (int nf = 0; nf < 4; nf++) {
                    MMA_F16(acc[mf][nf], a[mf], b0[nf]);   // A*Bhi
                    MMA_F16(acc[mf][nf], a[mf], b1[nf]);   // A*Blo
                }
        }
    }
    #undef ISSUE

    // ---- epilogue (undo x256 weight scale)
    const int er = lane >> 2;
    const int ec = (lane & 3) * 2;
    #pragma unroll
    for (int mf = 0; mf < 4; mf++) {
        const int row0 = rowBase + warpM * 64 + mf * 16 + er;
        #pragma unroll
        for (int nf = 0; nf < 4; nf++) {
            const int col = colBase + warpN * 32 + nf * 8 + ec;
            float2 v0 = make_float2(acc[mf][nf][0] * WSCALE_INV,
                                    acc[mf][nf][1] * WSCALE_INV);
            float2 v1 = make_float2(acc[mf][nf][2] * WSCALE_INV,
                                    acc[mf][nf][3] * WSCALE_INV);
            if (RES) {
                const float2 r0 = *(const float2*)(res + (size_t)row0 * DD + col);
                const float2 r1 = *(const float2*)(res + (size_t)(row0 + 8) * DD + col);
                v0.x += r0.x; v0.y += r0.y; v1.x += r1.x; v1.y += r1.y;
            }
            *(float2*)(C + (size_t)row0 * DD + col) = v0;
            *(float2*)(C + (size_t)(row0 + 8) * DD + col) = v1;
        }
    }
}

// ======================= A conversion (fp32 -> fp16) ========================
template<bool SC>
__global__ __launch_bounds__(256) void tohalf_kernel(
    const float* __restrict__ in0, const float* __restrict__ in1,
    __half* __restrict__ o, const float* __restrict__ g)
{
    const size_t e = ((size_t)blockIdx.x * 256 + threadIdx.x) * 8;
    const float* in = blockIdx.y ? in1 : in0;
    const size_t oz = (size_t)blockIdx.y * ((size_t)MM * DD);
    float4 v0 = *(const float4*)(in + e);
    float4 v1 = *(const float4*)(in + e + 4);
    if (SC) {
        const int b = (int)(e >> 21);
        const int d = (int)(e & (DD - 1));
        const float4 g0 = *(const float4*)(g + b * DD + d);
        const float4 g1 = *(const float4*)(g + b * DD + d + 4);
        v0.x *= g0.x; v0.y *= g0.y; v0.z *= g0.z; v0.w *= g0.w;
        v1.x *= g1.x; v1.y *= g1.y; v1.z *= g1.z; v1.w *= g1.w;
    }
    uint4 h = make_uint4(pack_h(v0.x, v0.y), pack_h(v0.z, v0.w),
                         pack_h(v1.x, v1.y), pack_h(v1.z, v1.w));
    *(uint4*)(o + oz + e) = h;
}

// ======================= weight transpose + split (x256) ====================
__global__ __launch_bounds__(256) void wsplit_kernel(
    const float* __restrict__ W0, const float* __restrict__ W1,
    __half* __restrict__ bhi, __half* __restrict__ blo)
{
    __shared__ float tile[32][33];
    const float* W = blockIdx.z ? W1 : W0;
    const size_t oz = (size_t)blockIdx.z * DD * DD;
    const int tx = threadIdx.x & 31, ty0 = threadIdx.x >> 5;
    const int nbase = blockIdx.x * 32, kbase = blockIdx.y * 32;
    #pragma unroll
    for (int j = 0; j < 4; j++) {
        int r = ty0 + j * 8;
        tile[r][tx] = W[(size_t)(kbase + r) * DD + nbase + tx];
    }
    __syncthreads();
    #pragma unroll
    for (int j = 0; j < 4; j++) {
        int n = nbase + ty0 + j * 8;
        int k = kbase + tx;
        float v = tile[tx][ty0 + j * 8] * WSCALE;
        __half h = __float2half_rn(v);
        float r = v - __half2float(h);
        bhi[oz + (size_t)n * DD + k] = h;
        blo[oz + (size_t)n * DD + k] = __float2half_rn(r);
    }
}

// ======================= small-W transpose (Wq/Wk -> Wt[h][d]) ==============
__global__ __launch_bounds__(256) void wtrans_kernel(
    const float* __restrict__ W0, const float* __restrict__ W1,
    float* __restrict__ Wt)
{
    const int idx = blockIdx.x * 256 + threadIdx.x;      // 0..16383
    const float* W = blockIdx.y ? W1 : W0;
    const int h = idx >> 10, d = idx & (DD - 1);
    Wt[blockIdx.y * (HH * DD) + idx] = W[d * HH + h];
}

// ======================= middle kernels =====================================
__global__ __launch_bounds__(256) void logits_kernel(
    const float* __restrict__ X, const float* __restrict__ Wt,
    const float* __restrict__ mask, float* __restrict__ logits)
{
    const int m = blockIdx.x;
    const int b = m >> 11;
    const int s = m & (SS - 1);
    const int tid = threadIdx.x;

    __shared__ float xs[DD];
    __shared__ float red[256];

    ((float4*)xs)[tid] = ((const float4*)(X + (size_t)m * DD))[tid];
    __syncthreads();

    const int h = tid >> 4, g = tid & 15;
    const float* wrow = Wt + h * DD;
    float acc = 0.f;
    #pragma unroll 8
    for (int j = 0; j < 64; j++)
        acc += xs[g + 16 * j] * wrow[g + 16 * j];

    red[tid] = acc;
    __syncthreads();
    if (tid < HH) {
        float v = 0.f;
        #pragma unroll
        for (int g2 = 0; g2 < 16; g2++) v += red[tid * 16 + g2];
        logits[((size_t)(b * HH + tid)) * SS + s] =
            v * 0.125f - (1.f - mask[m]) * 1e8f;
    }
}

__global__ __launch_bounds__(256) void k_logits_kernel(
    const float* __restrict__ K, const float* __restrict__ gq,
    const float* __restrict__ Wt, const float* __restrict__ mask,
    float* __restrict__ logits)
{
    const int m = blockIdx.x;
    const int b = m >> 11;
    const int s = m & (SS - 1);
    const int hp = s >> 7;
    const int sbase = (s & 127) * 16;
    const int tid = threadIdx.x;

    __shared__ float xs[DD];
    __shared__ float red[256];

    const float* gqr = gq + (size_t)(b * HH + hp) * DHH;
    #pragma unroll
    for (int t = 0; t < 4; t++) {
        const int idx = tid + t * 256;
        const int j = idx >> 6, dh = idx & 63;
        xs[idx] = K[((size_t)(b * SS + sbase + j)) * DD + hp * DHH + dh] * gqr[dh];
    }
    __syncthreads();

    const int h = tid >> 4, g = tid & 15;
    const float* wrow = Wt + h * DD;
    float acc = 0.f;
    #pragma unroll 8
    for (int j = 0; j < 64; j++)
        acc += xs[g + 16 * j] * wrow[g + 16 * j];

    red[tid] = acc;
    __syncthreads();
    if (tid < HH) {
        float v = 0.f;
        #pragma unroll
        for (int g2 = 0; g2 < 16; g2++) v += red[tid * 16 + g2];
        logits[((size_t)(b * HH + tid)) * SS + s] =
            v * 0.125f - (1.f - mask[m]) * 1e8f;
    }
}

template<bool GM>
__global__ __launch_bounds__(256) void softmax_wsum_kernel(
    const float* __restrict__ logits, const float* __restrict__ src,
    float* __restrict__ gout, const float* __restrict__ gmul)
{
    const int b = blockIdx.x >> 4, h = blockIdx.x & 15;
    const int tid = threadIdx.x;
    const float* lrow = logits + (size_t)(b * HH + h) * SS;

    __shared__ float att[SS];
    __shared__ float red[256];

    float mx = -3.4e38f;
    for (int s = tid; s < SS; s += 256) mx = fmaxf(mx, lrow[s]);
    red[tid] = mx; __syncthreads();
    for (int off = 128; off > 0; off >>= 1) {
        if (tid < off) red[tid] = fmaxf(red[tid], red[tid + off]);
        __syncthreads();
    }
    mx = red[0];
    __syncthreads();

    float sum = 0.f;
    for (int s = tid; s < SS; s += 256) {
        float e = expf(lrow[s] - mx);
        att[s] = e;
        sum += e;
    }
    red[tid] = sum; __syncthreads();
    for (int off = 128; off > 0; off >>= 1) {
        if (tid < off) red[tid] += red[tid + off];
        __syncthreads();
    }
    const float inv = 1.f / red[0];
    __syncthreads();

    const int dh = tid & 63, j = tid >> 6;
    const float* base = src + (size_t)b * (SS * DD) + h * DHH + dh;
    float acc = 0.f;
    for (int s = j; s < SS; s += 4)
        acc += att[s] * base[(size_t)s * DD];

    red[tid] = acc; __syncthreads();
    if (j == 0) {
        acc = red[dh] + red[64 + dh] + red[128 + dh] + red[192 + dh];
        float r = acc * inv;
        if (GM) r *= gmul[(b * HH + h) * DHH + dh];
        gout[(b * HH + h) * DHH + dh] = r;
    }
}

// ===========================================================================
extern "C" void kernel_launch(void* const* d_in, const int* in_sizes, int n_in,
                              void* d_out, int out_size)
{
    const float* Qseq  = (const float*)d_in[0];
    const float* Kseq  = (const float*)d_in[1];
    const float* Qmask = (const float*)d_in[2];
    const float* Kmask = (const float*)d_in[3];
    const float* WQ    = (const float*)d_in[4];
    const float* WK    = (const float*)d_in[5];
    const float* Wq    = (const float*)d_in[6];
    const float* Wk    = (const float*)d_in[7];
    const float* WP    = (const float*)d_in[8];
    float* out = (float*)d_out;

    float *pQ, *pK, *pL, *pgq, *pgk, *pWt;
    __half *pA, *pBhi, *pBlo;
    cudaGetSymbolAddress((void**)&pQ,   g_Q);
    cudaGetSymbolAddress((void**)&pK,   g_K);
    cudaGetSymbolAddress((void**)&pL,   g_logits);
    cudaGetSymbolAddress((void**)&pgq,  g_gq);
    cudaGetSymbolAddress((void**)&pgk,  g_gk);
    cudaGetSymbolAddress((void**)&pWt,  g_Wt);
    cudaGetSymbolAddress((void**)&pA,   g_Af16);
    cudaGetSymbolAddress((void**)&pBhi, g_Bhi);
    cudaGetSymbolAddress((void**)&pBlo, g_Blo);

    cudaFuncSetAttribute(hmma_gemm_kernel<false>,
                         cudaFuncAttributeMaxDynamicSharedMemorySize, GEMM_SMEM);
    cudaFuncSetAttribute(hmma_gemm_kernel<true>,
                         cudaFuncAttributeMaxDynamicSharedMemorySize, GEMM_SMEM);

    const int spB = (MM * DD) / 8 / 256;   // 8192 blocks per input

    // 0) transpose Wq/Wk for the logits kernels
    wtrans_kernel<<<dim3(64, 2), 256>>>(Wq, Wk, pWt);

    // 1+2) Q = Q_seq @ WQ and K = K_seq @ WK  (merged)
    tohalf_kernel<false><<<dim3(spB, 2), 256>>>(Qseq, Kseq, pA, nullptr);
    wsplit_kernel<<<dim3(32, 32, 2), 256>>>(WQ, WK, pBhi, pBlo);
    hmma_gemm_kernel<false><<<dim3(8, 128, 2), 256, GEMM_SMEM>>>(
        pA, pBhi, pBlo, pQ, pK, nullptr);

    // 3) q logits + softmax + global_q
    logits_kernel<<<MM, 256>>>(pQ, pWt, Qmask, pL);
    softmax_wsum_kernel<false><<<BB * HH, 256>>>(pL, pQ, pgq, nullptr);

    // 4) k logits (fused QK gather) + softmax + global_k (fused gq mul)
    k_logits_kernel<<<MM, 256>>>(pK, pgq, pWt + HH * DD, Kmask, pL);
    softmax_wsum_kernel<true><<<BB * HH, 256>>>(pL, pK, pgk, pgq);

    // 5) out = ((gk ⊙ Q) @ WP) + Q
    tohalf_kernel<true><<<dim3(spB, 1), 256>>>(pQ, nullptr, pA, pgk);
    wsplit_kernel<<<dim3(32, 32, 1), 256>>>(WP, WP, pBhi, pBlo);
    hmma_gemm_kernel<true><<<dim3(8, 128, 1), 256, GEMM_SMEM>>>(
        pA, pBhi, pBlo, out, out, pQ);
}

// round 10
// speedup vs baseline: 2.0121x; 2.0121x over previous
#include <cuda_runtime.h>
#include <cuda_fp16.h>
#include <math.h>
#include <stdint.h>

// Problem constants
#define BB   8
#define SS   2048
#define HH   16
#define DHH  64
#define DD   1024            // H*DH
#define MM   (BB*SS)         // 16384

#define WSCALE     256.0f
#define WSCALE_INV 0.00390625f

// ---------------- scratch (__device__ globals; allocation-free) -------------
__device__ float g_Q     [BB*SS*DD];     // Q = Q_seq @ WQ        (B,S,D)
__device__ float g_K     [BB*SS*DD];     // K = K_seq @ WK        (B,S,D)
__device__ float g_logits[BB*HH*SS];     // (B,H,S)
__device__ float g_gq    [BB*HH*DHH];
__device__ float g_gk    [BB*HH*DHH];
__device__ float g_Wt    [2*HH*DD];      // transposed Wq (slot0) / Wk (slot1)
__device__ __half g_Af16[2*MM*DD];       // fp16 A (2 slots for merged GEMM1/2)
__device__ __half g_Bf16[2*DD*DD];       // transposed weights Bt[n,k], x256, fp16

// ======================= PTX helpers ========================================
__device__ __forceinline__ uint32_t smem_to_u32(const void* p) {
    uint32_t a;
    asm("{ .reg .u64 t; cvta.to.shared.u64 t, %1; cvt.u32.u64 %0, t; }"
        : "=r"(a) : "l"(p));
    return a;
}
#define LDSM4(r, addr) asm volatile( \
    "ldmatrix.sync.aligned.m8n8.x4.shared.b16 {%0,%1,%2,%3}, [%4];" \
    : "=r"((r)[0]), "=r"((r)[1]), "=r"((r)[2]), "=r"((r)[3]) : "r"(addr))
#define MMA_F16(d, a, b) asm volatile( \
    "mma.sync.aligned.m16n8k16.row.col.f32.f16.f16.f32 " \
    "{%0,%1,%2,%3}, {%4,%5,%6,%7}, {%8,%9}, {%0,%1,%2,%3};" \
    : "+f"((d)[0]), "+f"((d)[1]), "+f"((d)[2]), "+f"((d)[3]) \
    : "r"((a)[0]), "r"((a)[1]), "r"((a)[2]), "r"((a)[3]), \
      "r"((b)[0]), "r"((b)[1]))
__device__ __forceinline__ void cp16(uint32_t dst, const void* src) {
    asm volatile("cp.async.cg.shared.global [%0], [%1], 16;"
                 :: "r"(dst), "l"(src) : "memory");
}
#define CP_COMMIT()  asm volatile("cp.async.commit_group;" ::: "memory")
#define CP_WAIT_1()  asm volatile("cp.async.wait_group 1;" ::: "memory")
#define CP_WAIT_0()  asm volatile("cp.async.wait_group 0;" ::: "memory")

__device__ __forceinline__ uint32_t pack_h(float a, float b) {
    __half2 t;
    t.x = __float2half_rn(a);
    t.y = __float2half_rn(b);
    return *(uint32_t*)&t;
}

// ======================= HMMA fp16 GEMM =====================================
// C[M,N=1024] = (1/256) * Af16 @ Bf16 (+res), B pre-scaled x256.
// CTA tile 128x128, BK=64, 8 warps (warp 64x32), 3-stage cp.async pipeline,
// XOR-swizzled 128B rows (conflict-free ldmatrix), 2 CTAs/SM.
// Stage: A [128][128B] @0, B [128][128B] @16384  (32 KB)
#define NST       3
#define STAGE_B   32768
#define GEMM_SMEM (NST * STAGE_B)     // 98304
#define KB2       16                  // 1024 / 64

template<bool RES>
__global__ __launch_bounds__(256, 2) void hmma_gemm_kernel(
    const __half* __restrict__ A, const __half* __restrict__ B,
    float* __restrict__ C0, float* __restrict__ C1,
    const float* __restrict__ res)
{
    extern __shared__ __align__(128) char smem[];
    const uint32_t sb = smem_to_u32(smem);
    const int tid = threadIdx.x;
    const int lane = tid & 31;
    const int wid  = tid >> 5;
    const int warpM = wid >> 2;            // 0..1
    const int warpN = wid & 3;             // 0..3
    const int colBase = blockIdx.x * 128;
    const int rowBase = blockIdx.y * 128;
    const int z = blockIdx.z;
    float* C = z ? C1 : C0;
    const size_t aZ = (size_t)z * MM * DD;
    const size_t bZ = (size_t)z * DD * DD;

    // ---- cp.async mapping: row = tid>>1, 4 x 16B chunks per half-row per buf
    const int crow = tid >> 1;                      // 0..127
    const int half = tid & 1;
    const int rsw  = crow & 7;
    uint32_t dOff[4];
    #pragma unroll
    for (int i = 0; i < 4; i++)
        dOff[i] = crow * 128 + (((half * 4 + i) ^ rsw) << 4);
    const char* pA = (const char*)(A + aZ + (size_t)(rowBase + crow) * DD) + half * 64;
    const char* pB = (const char*)(B + bZ + (size_t)(colBase + crow) * DD) + half * 64;

    #define ISSUE(s, kb) do {                                              \
        const uint32_t bs_ = sb + (s) * STAGE_B;                           \
        const int ko_ = (kb) * 128;                                        \
        _Pragma("unroll")                                                  \
        for (int i = 0; i < 4; i++) {                                      \
            cp16(bs_ + dOff[i],         pA + ko_ + i * 16);                \
            cp16(bs_ + 16384 + dOff[i], pB + ko_ + i * 16);                \
        }                                                                  \
        CP_COMMIT();                                                       \
    } while (0)

    // ---- ldmatrix row bases + swizzle keys
    const int lrow = lane & 15;
    const int hi16 = lane >> 4;
    uint32_t aRow[4]; int aSw[4];
    #pragma unroll
    for (int mf = 0; mf < 4; mf++) {
        const int r = warpM * 64 + mf * 16 + lrow;
        aRow[mf] = r * 128; aSw[mf] = r & 7;
    }
    uint32_t bRow[2]; int bSw[2];
    #pragma unroll
    for (int np = 0; np < 2; np++) {
        const int r = warpN * 32 + np * 16 + lrow;
        bRow[np] = r * 128; bSw[np] = r & 7;
    }

    ISSUE(0, 0);
    ISSUE(1, 1);

    float acc[4][4][4];
    #pragma unroll
    for (int mf = 0; mf < 4; mf++)
        #pragma unroll
        for (int nf = 0; nf < 4; nf++)
            #pragma unroll
            for (int q = 0; q < 4; q++) acc[mf][nf][q] = 0.f;

    for (int kb = 0; kb < KB2; kb++) {
        if (kb == KB2 - 1) { CP_WAIT_0(); } else { CP_WAIT_1(); }
        __syncthreads();
        if (kb + 2 < KB2) ISSUE((kb + 2) % NST, kb + 2);

        const uint32_t st = sb + (kb % NST) * STAGE_B;
        #pragma unroll
        for (int ks = 0; ks < 4; ks++) {
            const int ck = ks * 2 + hi16;
            uint32_t b0[4][2];
            #pragma unroll
            for (int np = 0; np < 2; np++) {
                uint32_t r[4];
                LDSM4(r, st + 16384 + bRow[np] + (((ck ^ bSw[np])) << 4));
                b0[np * 2 + 0][0] = r[0]; b0[np * 2 + 0][1] = r[2];
                b0[np * 2 + 1][0] = r[1]; b0[np * 2 + 1][1] = r[3];
            }
            uint32_t a[4][4];
            #pragma unroll
            for (int mf = 0; mf < 4; mf++)
                LDSM4(a[mf], st + aRow[mf] + (((ck ^ aSw[mf])) << 4));
            #pragma unroll
            for (int mf = 0; mf < 4; mf++)
                #pragma unroll
                for (int nf = 0; nf < 4; nf++)
                    MMA_F16(acc[mf][nf], a[mf], b0[nf]);
        }
    }
    #undef ISSUE

    // ---- epilogue (undo x256 weight scale)
    const int er = lane >> 2;
    const int ec = (lane & 3) * 2;
    #pragma unroll
    for (int mf = 0; mf < 4; mf++) {
        const int row0 = rowBase + warpM * 64 + mf * 16 + er;
        #pragma unroll
        for (int nf = 0; nf < 4; nf++) {
            const int col = colBase + warpN * 32 + nf * 8 + ec;
            float2 v0 = make_float2(acc[mf][nf][0] * WSCALE_INV,
                                    acc[mf][nf][1] * WSCALE_INV);
            float2 v1 = make_float2(acc[mf][nf][2] * WSCALE_INV,
                                    acc[mf][nf][3] * WSCALE_INV);
            if (RES) {
                const float2 r0 = *(const float2*)(res + (size_t)row0 * DD + col);
                const float2 r1 = *(const float2*)(res + (size_t)(row0 + 8) * DD + col);
                v0.x += r0.x; v0.y += r0.y; v1.x += r1.x; v1.y += r1.y;
            }
            *(float2*)(C + (size_t)row0 * DD + col) = v0;
            *(float2*)(C + (size_t)(row0 + 8) * DD + col) = v1;
        }
    }
}

// ======================= A conversion (fp32 -> fp16) ========================
template<bool SC>
__global__ __launch_bounds__(256) void tohalf_kernel(
    const float* __restrict__ in0, const float* __restrict__ in1,
    __half* __restrict__ o, const float* __restrict__ g)
{
    const size_t e = ((size_t)blockIdx.x * 256 + threadIdx.x) * 8;
    const float* in = blockIdx.y ? in1 : in0;
    const size_t oz = (size_t)blockIdx.y * ((size_t)MM * DD);
    float4 v0 = *(const float4*)(in + e);
    float4 v1 = *(const float4*)(in + e + 4);
    if (SC) {
        const int b = (int)(e >> 21);
        const int d = (int)(e & (DD - 1));
        const float4 g0 = *(const float4*)(g + b * DD + d);
        const float4 g1 = *(const float4*)(g + b * DD + d + 4);
        v0.x *= g0.x; v0.y *= g0.y; v0.z *= g0.z; v0.w *= g0.w;
        v1.x *= g1.x; v1.y *= g1.y; v1.z *= g1.z; v1.w *= g1.w;
    }
    uint4 h = make_uint4(pack_h(v0.x, v0.y), pack_h(v0.z, v0.w),
                         pack_h(v1.x, v1.y), pack_h(v1.z, v1.w));
    *(uint4*)(o + oz + e) = h;
}

// ======================= weight transpose (x256, fp16) ======================
__global__ __launch_bounds__(256) void wsplit_kernel(
    const float* __restrict__ W0, const float* __restrict__ W1,
    __half* __restrict__ bh)
{
    __shared__ float tile[32][33];
    const float* W = blockIdx.z ? W1 : W0;
    const size_t oz = (size_t)blockIdx.z * DD * DD;
    const int tx = threadIdx.x & 31, ty0 = threadIdx.x >> 5;
    const int nbase = blockIdx.x * 32, kbase = blockIdx.y * 32;
    #pragma unroll
    for (int j = 0; j < 4; j++) {
        int r = ty0 + j * 8;
        tile[r][tx] = W[(size_t)(kbase + r) * DD + nbase + tx];
    }
    __syncthreads();
    #pragma unroll
    for (int j = 0; j < 4; j++) {
        int n = nbase + ty0 + j * 8;
        int k = kbase + tx;
        bh[oz + (size_t)n * DD + k] = __float2half_rn(tile[tx][ty0 + j * 8] * WSCALE);
    }
}

// ======================= small-W transpose (Wq/Wk -> Wt[h][d]) ==============
__global__ __launch_bounds__(256) void wtrans_kernel(
    const float* __restrict__ W0, const float* __restrict__ W1,
    float* __restrict__ Wt)
{
    const int idx = blockIdx.x * 256 + threadIdx.x;      // 0..16383
    const float* W = blockIdx.y ? W1 : W0;
    const int h = idx >> 10, d = idx & (DD - 1);
    Wt[blockIdx.y * (HH * DD) + idx] = W[d * HH + h];
}

// ======================= middle kernels =====================================
__global__ __launch_bounds__(256) void logits_kernel(
    const float* __restrict__ X, const float* __restrict__ Wt,
    const float* __restrict__ mask, float* __restrict__ logits)
{
    const int m = blockIdx.x;
    const int b = m >> 11;
    const int s = m & (SS - 1);
    const int tid = threadIdx.x;

    __shared__ float xs[DD];
    __shared__ float red[256];

    ((float4*)xs)[tid] = ((const float4*)(X + (size_t)m * DD))[tid];
    __syncthreads();

    const int h = tid >> 4, g = tid & 15;
    const float* wrow = Wt + h * DD;
    float acc = 0.f;
    #pragma unroll 8
    for (int j = 0; j < 64; j++)
        acc += xs[g + 16 * j] * wrow[g + 16 * j];

    red[tid] = acc;
    __syncthreads();
    if (tid < HH) {
        float v = 0.f;
        #pragma unroll
        for (int g2 = 0; g2 < 16; g2++) v += red[tid * 16 + g2];
        logits[((size_t)(b * HH + tid)) * SS + s] =
            v * 0.125f - (1.f - mask[m]) * 1e8f;
    }
}

__global__ __launch_bounds__(256) void k_logits_kernel(
    const float* __restrict__ K, const float* __restrict__ gq,
    const float* __restrict__ Wt, const float* __restrict__ mask,
    float* __restrict__ logits)
{
    const int m = blockIdx.x;
    const int b = m >> 11;
    const int s = m & (SS - 1);
    const int hp = s >> 7;
    const int sbase = (s & 127) * 16;
    const int tid = threadIdx.x;

    __shared__ float xs[DD];
    __shared__ float red[256];

    const float* gqr = gq + (size_t)(b * HH + hp) * DHH;
    #pragma unroll
    for (int t = 0; t < 4; t++) {
        const int idx = tid + t * 256;
        const int j = idx >> 6, dh = idx & 63;
        xs[idx] = K[((size_t)(b * SS + sbase + j)) * DD + hp * DHH + dh] * gqr[dh];
    }
    __syncthreads();

    const int h = tid >> 4, g = tid & 15;
    const float* wrow = Wt + h * DD;
    float acc = 0.f;
    #pragma unroll 8
    for (int j = 0; j < 64; j++)
        acc += xs[g + 16 * j] * wrow[g + 16 * j];

    red[tid] = acc;
    __syncthreads();
    if (tid < HH) {
        float v = 0.f;
        #pragma unroll
        for (int g2 = 0; g2 < 16; g2++) v += red[tid * 16 + g2];
        logits[((size_t)(b * HH + tid)) * SS + s] =
            v * 0.125f - (1.f - mask[m]) * 1e8f;
    }
}

template<bool GM>
__global__ __launch_bounds__(256) void softmax_wsum_kernel(
    const float* __restrict__ logits, const float* __restrict__ src,
    float* __restrict__ gout, const float* __restrict__ gmul)
{
    const int b = blockIdx.x >> 4, h = blockIdx.x & 15;
    const int tid = threadIdx.x;
    const float* lrow = logits + (size_t)(b * HH + h) * SS;

    __shared__ float att[SS];
    __shared__ float red[256];

    float mx = -3.4e38f;
    for (int s = tid; s < SS; s += 256) mx = fmaxf(mx, lrow[s]);
    red[tid] = mx; __syncthreads();
    for (int off = 128; off > 0; off >>= 1) {
        if (tid < off) red[tid] = fmaxf(red[tid], red[tid + off]);
        __syncthreads();
    }
    mx = red[0];
    __syncthreads();

    float sum = 0.f;
    for (int s = tid; s < SS; s += 256) {
        float e = expf(lrow[s] - mx);
        att[s] = e;
        sum += e;
    }
    red[tid] = sum; __syncthreads();
    for (int off = 128; off > 0; off >>= 1) {
        if (tid < off) red[tid] += red[tid + off];
        __syncthreads();
    }
    const float inv = 1.f / red[0];
    __syncthreads();

    const int dh = tid & 63, j = tid >> 6;
    const float* base = src + (size_t)b * (SS * DD) + h * DHH + dh;
    float acc = 0.f;
    for (int s = j; s < SS; s += 4)
        acc += att[s] * base[(size_t)s * DD];

    red[tid] = acc; __syncthreads();
    if (j == 0) {
        acc = red[dh] + red[64 + dh] + red[128 + dh] + red[192 + dh];
        float r = acc * inv;
        if (GM) r *= gmul[(b * HH + h) * DHH + dh];
        gout[(b * HH + h) * DHH + dh] = r;
    }
}

// ===========================================================================
extern "C" void kernel_launch(void* const* d_in, const int* in_sizes, int n_in,
                              void* d_out, int out_size)
{
    const float* Qseq  = (const float*)d_in[0];
    const float* Kseq  = (const float*)d_in[1];
    const float* Qmask = (const float*)d_in[2];
    const float* Kmask = (const float*)d_in[3];
    const float* WQ    = (const float*)d_in[4];
    const float* WK    = (const float*)d_in[5];
    const float* Wq    = (const float*)d_in[6];
    const float* Wk    = (const float*)d_in[7];
    const float* WP    = (const float*)d_in[8];
    float* out = (float*)d_out;

    float *pQ, *pK, *pL, *pgq, *pgk, *pWt;
    __half *pA, *pB;
    cudaGetSymbolAddress((void**)&pQ,  g_Q);
    cudaGetSymbolAddress((void**)&pK,  g_K);
    cudaGetSymbolAddress((void**)&pL,  g_logits);
    cudaGetSymbolAddress((void**)&pgq, g_gq);
    cudaGetSymbolAddress((void**)&pgk, g_gk);
    cudaGetSymbolAddress((void**)&pWt, g_Wt);
    cudaGetSymbolAddress((void**)&pA,  g_Af16);
    cudaGetSymbolAddress((void**)&pB,  g_Bf16);

    cudaFuncSetAttribute(hmma_gemm_kernel<false>,
                         cudaFuncAttributeMaxDynamicSharedMemorySize, GEMM_SMEM);
    cudaFuncSetAttribute(hmma_gemm_kernel<true>,
                         cudaFuncAttributeMaxDynamicSharedMemorySize, GEMM_SMEM);

    const int spB = (MM * DD) / 8 / 256;   // 8192 blocks per input

    // 0) transpose Wq/Wk for the logits kernels
    wtrans_kernel<<<dim3(64, 2), 256>>>(Wq, Wk, pWt);

    // 1+2) Q = Q_seq @ WQ and K = K_seq @ WK  (merged)
    tohalf_kernel<false><<<dim3(spB, 2), 256>>>(Qseq, Kseq, pA, nullptr);
    wsplit_kernel<<<dim3(32, 32, 2), 256>>>(WQ, WK, pB);
    hmma_gemm_kernel<false><<<dim3(8, 128, 2), 256, GEMM_SMEM>>>(
        pA, pB, pQ, pK, nullptr);

    // 3) q logits + softmax + global_q
    logits_kernel<<<MM, 256>>>(pQ, pWt, Qmask, pL);
    softmax_wsum_kernel<false><<<BB * HH, 256>>>(pL, pQ, pgq, nullptr);

    // 4) k logits (fused QK gather) + softmax + global_k (fused gq mul)
    k_logits_kernel<<<MM, 256>>>(pK, pgq, pWt + HH * DD, Kmask, pL);
    softmax_wsum_kernel<true><<<BB * HH, 256>>>(pL, pK, pgk, pgq);

    // 5) out = ((gk ⊙ Q) @ WP) + Q
    tohalf_kernel<true><<<dim3(spB, 1), 256>>>(pQ, nullptr, pA, pgk);
    wsplit_kernel<<<dim3(32, 32, 1), 256>>>(WP, WP, pB);
    hmma_gemm_kernel<true><<<dim3(8, 128, 1), 256, GEMM_SMEM>>>(
        pA, pB, out, out, pQ);
}